// round 10
// baseline (speedup 1.0000x reference)
#include <cuda_runtime.h>
#include <cuda_bf16.h>
#include <math.h>
#include <stdint.h>

#define BATCH  64
#define HD     128
#define OUTC   10

#define PITCHV 136
#define V0_OFF 0
#define V1_OFF (16 * PITCHV * 2)
#define XS_OFF (2 * 16 * PITCHV * 2)
#define LG_OFF (XS_OFF + 16 * 256 * 4)
#define RI_OFF (LG_OFF + 64)
#define LT_OFF (RI_OFF + 64)
#define SMEM_MAIN (LT_OFF + 64)

// Pair products, fragment-permuted (bf16 as u32 pairs, 16.6 MB):
//  pair p covers sites (2p+1, 2p+2) i.e. cores[2p], cores[2p+1]
//  M[k][n] with n = 4h+c, c = a_idx + 2*b_idx combo; 512 n-cols.
//  u32 index: ((((p*8+wc)*8+nt)*4+kp)*32 + lane)*4 + j
//    kc=2kp+(j>>1); k0=kc*16+2*(lane&3)+((j&1)<<3); n=wc*64+nt*8+(lane>>2)
__device__ uint32_t g_pairperm[(size_t)127 * 32768];
// row-major temp for pair products: [p][c][k][h]
__device__ __nv_bfloat16 g_pairtmp[(size_t)127 * 4 * 128 * 128];
// last site (cores[254]) in old single-site fragment layout (n = 2h+d)
__device__ uint32_t g_perm_last[16384];

// ---------------- helpers ----------------
__device__ __forceinline__ uint32_t smem_u32(const void* p) {
    uint32_t a;
    asm("{ .reg .u64 t; cvta.to.shared.u64 t, %1; cvt.u32.u64 %0, t; }" : "=r"(a) : "l"(p));
    return a;
}
__device__ __forceinline__ void ldm_x4(uint32_t* r, uint32_t addr) {
    asm volatile("ldmatrix.sync.aligned.m8n8.x4.shared.b16 {%0,%1,%2,%3}, [%4];"
                 : "=r"(r[0]), "=r"(r[1]), "=r"(r[2]), "=r"(r[3]) : "r"(addr));
}
__device__ __forceinline__ void ldm_x4_t(uint32_t* r, uint32_t addr) {
    asm volatile("ldmatrix.sync.aligned.m8n8.x4.trans.shared.b16 {%0,%1,%2,%3}, [%4];"
                 : "=r"(r[0]), "=r"(r[1]), "=r"(r[2]), "=r"(r[3]) : "r"(addr));
}
__device__ __forceinline__ void mma16816(float* c, const uint32_t* a,
                                         uint32_t b0, uint32_t b1) {
    asm volatile(
        "mma.sync.aligned.m16n8k16.row.col.f32.bf16.bf16.f32 "
        "{%0,%1,%2,%3}, {%4,%5,%6,%7}, {%8,%9}, {%0,%1,%2,%3};"
        : "+f"(c[0]), "+f"(c[1]), "+f"(c[2]), "+f"(c[3])
        : "r"(a[0]), "r"(a[1]), "r"(a[2]), "r"(a[3]), "r"(b0), "r"(b1));
}
__device__ __forceinline__ uint32_t packbf2(float a, float b) {
    __nv_bfloat162 t = __floats2bfloat162_rn(a, b);
    return *reinterpret_cast<uint32_t*>(&t);
}

// ---------------- pair-product kernel: P_c = A_{a} @ B_{b} (128x128 bf16) ----
__global__ void __launch_bounds__(256) pp_kernel(const float* __restrict__ cores)
{
    extern __shared__ char psm[];
    __nv_bfloat16 (*As)[136] = (__nv_bfloat16 (*)[136])psm;
    __nv_bfloat16 (*Bs)[136] = (__nv_bfloat16 (*)[136])(psm + 128 * 136 * 2);
    const int c = blockIdx.x, p = blockIdx.y;
    const int aidx = c & 1, bidx = c >> 1;
    const int tid = threadIdx.x, lane = tid & 31, wid = tid >> 5;
    const int wr = wid >> 2, wcol = wid & 3;
    const float* pa = cores + (size_t)(2 * p) * 32768;
    const float* pb = cores + (size_t)(2 * p + 1) * 32768;

    #pragma unroll 4
    for (int it = 0; it < 64; ++it) {
        int idx = it * 256 + tid;
        int k = idx >> 7, j = idx & 127;
        float a0 = pa[(size_t)k * 256 + j], a1 = pa[(size_t)k * 256 + 128 + j];
        As[k][j] = __float2bfloat16(aidx ? (a1 - a0) : a0);
        float b0 = pb[(size_t)k * 256 + j], b1 = pb[(size_t)k * 256 + 128 + j];
        Bs[k][j] = __float2bfloat16(bidx ? (b1 - b0) : b0);
    }
    __syncthreads();

    const int l15 = lane & 15, lhi = (lane >> 4) << 3;
    float acc[4][4][4];
    #pragma unroll
    for (int i = 0; i < 4; ++i)
        #pragma unroll
        for (int j = 0; j < 4; ++j)
            #pragma unroll
            for (int v = 0; v < 4; ++v) acc[i][j][v] = 0.f;

    #pragma unroll
    for (int kc = 0; kc < 8; ++kc) {
        uint32_t a[4][4], bf[2][4];
        #pragma unroll
        for (int mi = 0; mi < 4; ++mi)
            ldm_x4(a[mi], smem_u32(&As[wr * 64 + mi * 16 + l15][kc * 16 + lhi]));
        #pragma unroll
        for (int nb = 0; nb < 2; ++nb)
            ldm_x4_t(bf[nb], smem_u32(&Bs[kc * 16 + l15][wcol * 32 + nb * 16 + lhi]));
        #pragma unroll
        for (int mi = 0; mi < 4; ++mi)
            #pragma unroll
            for (int nj = 0; nj < 4; ++nj)
                mma16816(acc[mi][nj], a[mi], bf[nj >> 1][(nj & 1) * 2], bf[nj >> 1][(nj & 1) * 2 + 1]);
    }

    char* outp = (char*)(g_pairtmp + (((size_t)p * 4 + c) << 14));
    const int g = lane >> 2, q = lane & 3;
    #pragma unroll
    for (int mi = 0; mi < 4; ++mi) {
        int r0 = wr * 64 + mi * 16 + g;
        #pragma unroll
        for (int nj = 0; nj < 4; ++nj) {
            int col = wcol * 32 + nj * 8 + q * 2;
            *(uint32_t*)(outp + (size_t)r0 * 256 + col * 2) = packbf2(acc[mi][nj][0], acc[mi][nj][1]);
            *(uint32_t*)(outp + (size_t)(r0 + 8) * 256 + col * 2) = packbf2(acc[mi][nj][2], acc[mi][nj][3]);
        }
    }
}

// ---------------- permute pair products into fragment order ----------------
__global__ void __launch_bounds__(256) perm_pairs()
{
    size_t gid = (size_t)blockIdx.x * 256 + threadIdx.x;   // 127*32768
    int u = (int)(gid & 32767);
    int p = (int)(gid >> 15);
    int j    = u & 3;
    int lane = (u >> 2) & 31;
    int kp   = (u >> 7) & 3;
    int nt   = (u >> 9) & 7;
    int wc   = (u >> 12) & 7;
    int kc = 2 * kp + (j >> 1);
    int k0 = kc * 16 + 2 * (lane & 3) + ((j & 1) << 3);
    int n  = wc * 64 + nt * 8 + (lane >> 2);
    int c = n & 3, h = n >> 2;
    const __nv_bfloat16* base = g_pairtmp + (((size_t)p * 4 + c) << 14);
    float lo = __bfloat162float(base[(size_t)k0 * 128 + h]);
    float hi = __bfloat162float(base[(size_t)(k0 + 1) * 128 + h]);
    g_pairperm[gid] = packbf2(lo, hi);
}

// ---------------- last-site fragment permute (old layout, m=254) ------------
__global__ void __launch_bounds__(256) conv_last(const float* __restrict__ cores)
{
    int u = blockIdx.x * 256 + threadIdx.x;   // 16384
    int j    = u & 3;
    int lane = (u >> 2) & 31;
    int kp   = (u >> 7) & 3;
    int nt   = (u >> 9) & 3;
    int wc   = (u >> 11) & 7;
    int kc = 2 * kp + (j >> 1);
    int k0 = kc * 16 + 2 * (lane & 3) + ((j & 1) << 3);
    int n  = wc * 32 + nt * 8 + (lane >> 2);
    int h = n >> 1, d = n & 1;
    const float* base = cores + (size_t)254 * 32768;
    float lo = base[(size_t)k0 * 256 + d * 128 + h];
    float hi = base[(size_t)(k0 + 1) * 256 + d * 128 + h];
    g_perm_last[u] = packbf2(lo, hi);
}

// ---------------- renorm helper ----------------
__device__ __forceinline__ void renorm(char* vw, char* sm) {
    float* LOGS = (float*)(sm + LG_OFF);
    float* RINV = (float*)(sm + RI_OFF);
    const int tid = threadIdx.x;
    __syncthreads();
    int bb = tid >> 4, seg = tid & 15;
    __nv_bfloat16* vrow = (__nv_bfloat16*)(vw + bb * (PITCHV * 2));
    float s = 0.f;
    #pragma unroll
    for (int j = 0; j < 8; ++j) {
        float f = __bfloat162float(vrow[seg * 8 + j]);
        s = fmaf(f, f, s);
    }
    #pragma unroll
    for (int o = 8; o > 0; o >>= 1) s += __shfl_xor_sync(0xffffffffu, s, o);
    if (seg == 0) {
        float nrm = fmaxf(sqrtf(s), 1e-30f);
        LOGS[bb] += logf(nrm);
        RINV[bb] = 1.f / nrm;
    }
    __syncthreads();
    float ri = RINV[bb];
    #pragma unroll
    for (int j = 0; j < 8; ++j)
        vrow[seg * 8 + j] = __float2bfloat16(__bfloat162float(vrow[seg * 8 + j]) * ri);
}

// ---------------- one pair step: V <- V * (M_{2p+1} M_{2p+2}) ----------------
__device__ __forceinline__ void pair_step(
    int p, uint4* __restrict__ H, const uint4* __restrict__ next_ptr,
    char* sm, uint32_t smb, int vro, int vwo,
    int lane, int wc, int l15, int lhi, int r, int q)
{
    float* XS = (float*)(sm + XS_OFF);

    // load half1 (nt 4..7) of pair p
    const uint4* bp1 = (const uint4*)g_pairperm + ((size_t)p << 13) + (uint32_t)(wc * 1024 + 512) + lane;
    uint4 H1[16];
    #pragma unroll
    for (int i = 0; i < 16; ++i) H1[i] = bp1[i * 32];

    __syncthreads();   // V(p) visible

    uint32_t A[8][4];
    #pragma unroll
    for (int kc = 0; kc < 8; ++kc)
        ldm_x4(A[kc], smb + vro + (uint32_t)(l15 * PITCHV + kc * 16 + lhi) * 2);

    float acc[8][4];
    #pragma unroll
    for (int i = 0; i < 8; ++i)
        #pragma unroll
        for (int j = 0; j < 4; ++j) acc[i][j] = 0.f;

    #pragma unroll
    for (int kc = 0; kc < 8; ++kc)
        #pragma unroll
        for (int nt = 0; nt < 4; ++nt) {
            const uint4& v = H[nt * 4 + (kc >> 1)];
            uint32_t b0 = (kc & 1) ? v.z : v.x;
            uint32_t b1 = (kc & 1) ? v.w : v.y;
            mma16816(acc[nt], A[kc], b0, b1);
        }

    // prefetch half0 of NEXT consumer into H (covered by second MMA block)
    #pragma unroll
    for (int i = 0; i < 16; ++i) H[i] = next_ptr[i * 32];

    #pragma unroll
    for (int kc = 0; kc < 8; ++kc)
        #pragma unroll
        for (int nt = 0; nt < 4; ++nt) {
            const uint4& v = H1[nt * 4 + (kc >> 1)];
            uint32_t b0 = (kc & 1) ? v.z : v.x;
            uint32_t b1 = (kc & 1) ? v.w : v.y;
            mma16816(acc[4 + nt], A[kc], b0, b1);
        }

    // combine combos: V_new[h] = (1 + ...) per expansion; c = n&3, n = 4h+c
    char* vw = sm + vwo;
    const float xa_r = XS[r * 256 + 2 * p + 1],       xb_r = XS[r * 256 + 2 * p + 2];
    const float xa_s = XS[(r + 8) * 256 + 2 * p + 1], xb_s = XS[(r + 8) * 256 + 2 * p + 2];
    const bool hi_c = (q & 1);
    #pragma unroll
    for (int nt = 0; nt < 8; ++nt) {
        float t0 = fmaf(xa_r, acc[nt][1], acc[nt][0]);
        float t1 = fmaf(xa_s, acc[nt][3], acc[nt][2]);
        if (hi_c) { t0 *= xb_r; t1 *= xb_s; }
        t0 += __shfl_xor_sync(0xffffffffu, t0, 1);
        t1 += __shfl_xor_sync(0xffffffffu, t1, 1);
        if (!hi_c) {
            int h = wc * 16 + nt * 2 + (q >> 1);
            *(__nv_bfloat16*)(vw + r * (PITCHV * 2) + h * 2) = __float2bfloat16(t0);
            *(__nv_bfloat16*)(vw + (r + 8) * (PITCHV * 2) + h * 2) = __float2bfloat16(t1);
        }
    }

    if (((p + 1) & 7) == 0 && p < 126) renorm(vw, sm);
}

// ---------------- single last-site step (old layout) ----------------
__device__ __forceinline__ void single_step(
    const uint4* __restrict__ H,
    char* sm, uint32_t smb, int vro, int vwo,
    int lane, int wc, int l15, int lhi, int r, int q)
{
    float* XS = (float*)(sm + XS_OFF);
    __syncthreads();

    uint32_t A[8][4];
    #pragma unroll
    for (int kc = 0; kc < 8; ++kc)
        ldm_x4(A[kc], smb + vro + (uint32_t)(l15 * PITCHV + kc * 16 + lhi) * 2);

    float acc[4][4];
    #pragma unroll
    for (int i = 0; i < 4; ++i)
        #pragma unroll
        for (int j = 0; j < 4; ++j) acc[i][j] = 0.f;

    #pragma unroll
    for (int kc = 0; kc < 8; ++kc)
        #pragma unroll
        for (int nt = 0; nt < 4; ++nt) {
            const uint4& v = H[nt * 4 + (kc >> 1)];
            uint32_t b0 = (kc & 1) ? v.z : v.x;
            uint32_t b1 = (kc & 1) ? v.w : v.y;
            mma16816(acc[nt], A[kc], b0, b1);
        }

    char* vw = sm + vwo;
    const float xa = XS[r * 256 + 255];
    const float xb = XS[(r + 8) * 256 + 255];
    #pragma unroll
    for (int nt = 0; nt < 4; ++nt) {
        int h = wc * 16 + nt * 4 + q;
        float v0 = fmaf(xa, acc[nt][1], (1.f - xa) * acc[nt][0]);
        float v1 = fmaf(xb, acc[nt][3], (1.f - xb) * acc[nt][2]);
        *(__nv_bfloat16*)(vw + r * (PITCHV * 2) + h * 2) = __float2bfloat16(v0);
        *(__nv_bfloat16*)(vw + (r + 8) * (PITCHV * 2) + h * 2) = __float2bfloat16(v1);
    }
}

// ---------------- main chain kernel ----------------
__global__ void __launch_bounds__(256, 1) mps_chain(
    const float* __restrict__ x, const float* __restrict__ core0,
    const float* __restrict__ classifier, float* __restrict__ out)
{
    __shared__ char sm[SMEM_MAIN];
    uint32_t smb = smem_u32(sm);
    const int tid = threadIdx.x, lane = tid & 31, wc = tid >> 5;
    const int b0 = blockIdx.x * 16;

    float* XS   = (float*)(sm + XS_OFF);
    float* LOGS = (float*)(sm + LG_OFF);
    float* RINV = (float*)(sm + RI_OFF);
    float* LTOT = (float*)(sm + LT_OFF);

    #pragma unroll
    for (int it = 0; it < 16; ++it) {
        int idx = it * 256 + tid;
        XS[idx] = x[(size_t)(b0 + (idx >> 8)) * 256 + (idx & 255)];
    }
    if (tid < 16) LOGS[tid] = 0.f;
    __syncthreads();

    #pragma unroll
    for (int it = 0; it < 8; ++it) {
        int idx = it * 256 + tid;
        int bb = idx >> 7, h = idx & 127;
        float xv = XS[bb * 256];
        float v = (1.f - xv) * core0[h] + xv * core0[HD + h];
        *(__nv_bfloat16*)(sm + V0_OFF + bb * (PITCHV * 2) + h * 2) = __float2bfloat16(v);
    }

    const int l15 = lane & 15, lhi = (lane >> 4) << 3;
    const int r = lane >> 2, q = lane & 3;

    // preload half0 of pair 0
    uint4 H[16];
    {
        const uint4* bp = (const uint4*)g_pairperm + (uint32_t)(wc * 1024) + lane;
        #pragma unroll
        for (int i = 0; i < 16; ++i) H[i] = bp[i * 32];
    }

    const uint4* lastbase = (const uint4*)g_perm_last + (uint32_t)(wc * 512) + lane;

    for (int pp = 0; pp < 63; ++pp) {
        int p0 = 2 * pp;
        const uint4* n0 = (const uint4*)g_pairperm + ((size_t)(p0 + 1) << 13) + (uint32_t)(wc * 1024) + lane;
        pair_step(p0, H, n0, sm, smb, V0_OFF, V1_OFF, lane, wc, l15, lhi, r, q);
        const uint4* n1 = (const uint4*)g_pairperm + ((size_t)(p0 + 2) << 13) + (uint32_t)(wc * 1024) + lane;
        pair_step(p0 + 1, H, n1, sm, smb, V1_OFF, V0_OFF, lane, wc, l15, lhi, r, q);
    }
    // p = 126: next consumer is the last single site
    pair_step(126, H, lastbase, sm, smb, V0_OFF, V1_OFF, lane, wc, l15, lhi, r, q);
    single_step(H, sm, smb, V1_OFF, V0_OFF, lane, wc, l15, lhi, r, q);
    __syncthreads();

    // final norm + total log (V in V0)
    {
        int bb = tid >> 4, seg = tid & 15;
        const __nv_bfloat16* vrow = (const __nv_bfloat16*)(sm + V0_OFF + bb * (PITCHV * 2));
        float s = 0.f;
        #pragma unroll
        for (int j = 0; j < 8; ++j) {
            float f = __bfloat162float(vrow[seg * 8 + j]);
            s = fmaf(f, f, s);
        }
        #pragma unroll
        for (int o = 8; o > 0; o >>= 1) s += __shfl_xor_sync(0xffffffffu, s, o);
        if (seg == 0) {
            float nrm = fmaxf(sqrtf(s), 1e-30f);
            RINV[bb] = 1.f / nrm;
            LTOT[bb] = LOGS[bb] + logf(nrm);
        }
    }
    __syncthreads();

    if (tid < 16 * OUTC) {
        int bb = tid / OUTC, o = tid % OUTC;
        const __nv_bfloat16* vrow = (const __nv_bfloat16*)(sm + V0_OFF + bb * (PITCHV * 2));
        float s = 0.f;
        #pragma unroll
        for (int h = 0; h < HD; ++h)
            s = fmaf(__bfloat162float(vrow[h]), classifier[o * HD + h], s);
        out[(size_t)(b0 + bb) * OUTC + o] = s * RINV[bb] + LTOT[bb];
    }
}

extern "C" void kernel_launch(void* const* d_in, const int* in_sizes, int n_in,
                              void* d_out, int out_size)
{
    (void)in_sizes; (void)n_in; (void)out_size;
    const float* x          = (const float*)d_in[0];
    const float* core0      = (const float*)d_in[1];
    const float* cores      = (const float*)d_in[2];
    const float* classifier = (const float*)d_in[3];
    float*       out        = (float*)d_out;

    cudaFuncSetAttribute(pp_kernel, cudaFuncAttributeMaxDynamicSharedMemorySize, 128 * 136 * 2 * 2);

    pp_kernel<<<dim3(4, 127), 256, 128 * 136 * 2 * 2>>>(cores);
    perm_pairs<<<16256, 256>>>();            // 127*32768 threads
    conv_last<<<64, 256>>>(cores);
    mps_chain<<<4, 256>>>(x, core0, classifier, out);
}